// round 13
// baseline (speedup 1.0000x reference)
#include <cuda_runtime.h>
#include <cuda_fp16.h>
#include <math.h>
#include <stdint.h>

#define Bsz  4
#define Tn   2048
#define Dm   768
#define Hn   12
#define HDm  64
#define MLPD 3072
#define WIN  256
#define NT   (Bsz * Tn)   /* 8192 rows */

#define QSC 0.18033688011112043f   /* 0.125 * log2(e) */

// ---------------- static scratch ----------------
__device__ __half g_xnh  [NT * Dm];
__device__ __half g_qkvh [NT * 3 * Dm];
__device__ __half g_attnh[NT * Dm];
__device__ __half g_hh   [NT * MLPD];
__device__ float  g_x1   [NT * Dm];
__device__ __half g_wqkvh[3 * Dm * Dm];
__device__ __half g_owh  [Dm * Dm];
__device__ __half g_w1h  [MLPD * Dm];
__device__ __half g_w2h  [Dm * MLPD];

__device__ __forceinline__ uint32_t smem_u32(const void* p) {
    uint32_t a;
    asm("{ .reg .u64 t; cvta.to.shared.u64 t, %1; cvt.u32.u64 %0, t; }"
        : "=r"(a) : "l"(p));
    return a;
}
__device__ __forceinline__ float ex2f(float x) {
    float y;
    asm("ex2.approx.f32 %0, %1;" : "=f"(y) : "f"(x));
    return y;
}

#define CPA16(dst, src) \
    asm volatile("cp.async.cg.shared.global [%0], [%1], 16;" \
                 :: "r"(dst), "l"(src) : "memory")
#define CPA_COMMIT() asm volatile("cp.async.commit_group;" ::: "memory")
#define CPA_WAIT1()  asm volatile("cp.async.wait_group 1;" ::: "memory")
#define CPA_WAIT0()  asm volatile("cp.async.wait_group 0;" ::: "memory")

#define LDSM4(r, addr)                                                        \
    asm volatile("ldmatrix.sync.aligned.m8n8.x4.shared.b16 {%0,%1,%2,%3}, [%4];" \
        : "=r"((r)[0]), "=r"((r)[1]), "=r"((r)[2]), "=r"((r)[3]) : "r"(addr))
#define LDSM4T(r, addr)                                                       \
    asm volatile("ldmatrix.sync.aligned.m8n8.x4.trans.shared.b16 {%0,%1,%2,%3}, [%4];" \
        : "=r"((r)[0]), "=r"((r)[1]), "=r"((r)[2]), "=r"((r)[3]) : "r"(addr))

#define MMA_F16(c, A0, A1, A2, A3, B0, B1)                               \
    asm volatile(                                                        \
        "mma.sync.aligned.m16n8k16.row.col.f32.f16.f16.f32 "             \
        "{%0,%1,%2,%3}, {%4,%5,%6,%7}, {%8,%9}, {%0,%1,%2,%3};"          \
        : "+f"((c)[0]), "+f"((c)[1]), "+f"((c)[2]), "+f"((c)[3])         \
        : "r"(A0), "r"(A1), "r"(A2), "r"(A3), "r"(B0), "r"(B1))

__device__ __forceinline__ uint32_t packh2(float a, float b) {
    __half2 h = __floats2half2_rn(a, b);
    return *(uint32_t*)&h;
}

// ---------------- fused fp32 -> fp16 conversion (all 4 weight tensors) ----------------
__global__ void __launch_bounds__(256) f2h4_kernel(
    const float* __restrict__ s0, const float* __restrict__ s1,
    const float* __restrict__ s2, const float* __restrict__ s3,
    __half* __restrict__ d0, __half* __restrict__ d1,
    __half* __restrict__ d2, __half* __restrict__ d3)
{
    int blk = blockIdx.x;
    const float* s; __half* d;
    if      (blk < 864)  { s = s0; d = d0; }
    else if (blk < 1152) { s = s1; d = d1; blk -= 864; }
    else if (blk < 2304) { s = s2; d = d2; blk -= 1152; }
    else                 { s = s3; d = d3; blk -= 2304; }
    const int i = blk * 2048 + threadIdx.x * 8;
    const float4 a = *(const float4*)(s + i);
    const float4 b = *(const float4*)(s + i + 4);
    *(__half2*)(d + i)     = __floats2half2_rn(a.x, a.y);
    *(__half2*)(d + i + 2) = __floats2half2_rn(a.z, a.w);
    *(__half2*)(d + i + 4) = __floats2half2_rn(b.x, b.y);
    *(__half2*)(d + i + 6) = __floats2half2_rn(b.z, b.w);
}

// ---------------- LayerNorm: 2 rows per 384-thread block ----------------
__global__ void __launch_bounds__(384) ln_kernel(const float* __restrict__ x,
                                                 const float* __restrict__ g,
                                                 const float* __restrict__ b,
                                                 __half* __restrict__ y)
{
    const int t   = threadIdx.x;
    const int grp = t / 192;
    const int lt  = t - grp * 192;
    const int row = blockIdx.x * 2 + grp;
    const float4 v = *(const float4*)(x + (size_t)row * Dm + lt * 4);

    float s  = v.x + v.y + v.z + v.w;
    float s2 = v.x * v.x + v.y * v.y + v.z * v.z + v.w * v.w;
    __shared__ float red[24];
#pragma unroll
    for (int o = 16; o > 0; o >>= 1) {
        s  += __shfl_xor_sync(0xffffffffu, s,  o);
        s2 += __shfl_xor_sync(0xffffffffu, s2, o);
    }
    const int w = t >> 5;   // 0..11
    if ((t & 31) == 0) { red[w] = s; red[12 + w] = s2; }
    __syncthreads();
    s = 0.f; s2 = 0.f;
#pragma unroll
    for (int i = 0; i < 6; i++) { s += red[grp * 6 + i]; s2 += red[12 + grp * 6 + i]; }

    const float mean = s * (1.0f / Dm);
    float var = s2 * (1.0f / Dm) - mean * mean;
    var = fmaxf(var, 0.0f);
    const float rstd = rsqrtf(var + 1e-5f);

    const float4 g4 = *(const float4*)(g + lt * 4);
    const float4 b4 = *(const float4*)(b + lt * 4);
    __half* yr = y + (size_t)row * Dm + lt * 4;
    *(__half2*)(yr)     = __floats2half2_rn((v.x - mean) * rstd * g4.x + b4.x,
                                            (v.y - mean) * rstd * g4.y + b4.y);
    *(__half2*)(yr + 2) = __floats2half2_rn((v.z - mean) * rstd * g4.z + b4.z,
                                            (v.w - mean) * rstd * g4.w + b4.w);
}

// ---------------- fp16 GEMM: cp.async + ldmatrix + mma.m16n8k16 ----------------
// C[M,N] = A[M,K] @ B[N,K]^T + bias (+res) (+gelu) (+Q prescale). TBM = 128 or 64.
#define BN 128
#define BKH 64
#define STAGES 3
#define BSTG 16384

template<int GELU, int RES, int OUTH, int TBM, int SCQ>
__global__ void __launch_bounds__(256, 2) gemm_h_kernel(
    const __half* __restrict__ A,
    const __half* __restrict__ B,
    const float* __restrict__ bias,
    const float* __restrict__ res,
    void* __restrict__ Cv,
    int M, int N, int K)
{
    constexpr int WROWS = TBM / 2;
    constexpr int MT    = WROWS / 16;
    constexpr int AIT   = TBM / 32;
    constexpr int ASTG  = TBM * 128;

    extern __shared__ char sh[];
    const uint32_t sA = smem_u32(sh);
    const uint32_t sB = sA + STAGES * ASTG;

    const int t    = threadIdx.x;
    const int lane = t & 31;
    const int warp = t >> 5;
    const int wm   = warp & 1;
    const int wn   = warp >> 1;
    const int bm   = blockIdx.y * TBM;
    const int bn   = blockIdx.x * BN;

    const int cm  = t >> 3;
    const int ckq = t & 7;
    const uint32_t daBase = cm * 128 + (uint32_t)((ckq ^ (cm & 7)) << 4);
    const __half* Ag = A + (size_t)(bm + cm) * K + ckq * 8;
    const __half* Bg = B + (size_t)(bn + cm) * K + ckq * 8;

    const int l15 = lane & 15;
    const int lk  = lane >> 4;
    const int l7  = lane & 7;
    uint32_t aoff[MT], boff[2];
#pragma unroll
    for (int mt = 0; mt < MT; mt++) aoff[mt] = (uint32_t)((wm * WROWS + mt * 16 + l15) * 128);
#pragma unroll
    for (int n2 = 0; n2 < 2; n2++) boff[n2] = (uint32_t)((wn * 32 + n2 * 16 + l15) * 128);

    float acc[MT][4][4];
#pragma unroll
    for (int mt = 0; mt < MT; mt++)
#pragma unroll
        for (int nt = 0; nt < 4; nt++)
#pragma unroll
            for (int q = 0; q < 4; q++) acc[mt][nt][q] = 0.f;

    const int nch = K / BKH;

    auto issue = [&](int ch, int s) {
        const __half* ag = Ag + ch * BKH;
        const __half* bg = Bg + ch * BKH;
        const uint32_t da = sA + s * ASTG + daBase;
        const uint32_t db = sB + s * BSTG + daBase;
#pragma unroll
        for (int i = 0; i < AIT; i++)
            CPA16(da + i * 32 * 128, ag + (size_t)i * 32 * K);
#pragma unroll
        for (int i = 0; i < 4; i++)
            CPA16(db + i * 32 * 128, bg + (size_t)i * 32 * K);
    };

    issue(0, 0); CPA_COMMIT();
    issue(1, 1); CPA_COMMIT();

    for (int ch = 0; ch < nch; ch++) {
        CPA_WAIT1();
        __syncthreads();
        if (ch + 2 < nch) issue(ch + 2, (ch + 2) % STAGES);
        CPA_COMMIT();

        const uint32_t baA = sA + (ch % STAGES) * ASTG;
        const uint32_t baB = sB + (ch % STAGES) * BSTG;
#pragma unroll
        for (int ks = 0; ks < 4; ks++) {
            const uint32_t sw = (uint32_t)(((2 * ks + lk) ^ l7) << 4);
            uint32_t a[MT][4], b[2][4];
#pragma unroll
            for (int mt = 0; mt < MT; mt++) LDSM4(a[mt], baA + aoff[mt] + sw);
#pragma unroll
            for (int n2 = 0; n2 < 2; n2++) LDSM4(b[n2], baB + boff[n2] + sw);
#pragma unroll
            for (int mt = 0; mt < MT; mt++)
#pragma unroll
                for (int nt = 0; nt < 4; nt++)
                    MMA_F16(acc[mt][nt],
                            a[mt][0], a[mt][1], a[mt][2], a[mt][3],
                            b[nt >> 1][nt & 1], b[nt >> 1][2 + (nt & 1)]);
        }
    }

    // ---- epilogue ----
    const int g  = lane >> 2;
    const int l4 = lane & 3;
    const float qm = (SCQ && bn < Dm) ? QSC : 1.0f;   // prescale Q columns (log2-domain softmax)
#pragma unroll
    for (int mt = 0; mt < MT; mt++) {
        const int r0 = bm + wm * WROWS + mt * 16 + g;
#pragma unroll
        for (int nt = 0; nt < 4; nt++) {
            const int col = bn + wn * 32 + nt * 8 + l4 * 2;
            const float2 bia = *(const float2*)(bias + col);
            float v00 = acc[mt][nt][0] + bia.x, v01 = acc[mt][nt][1] + bia.y;
            float v10 = acc[mt][nt][2] + bia.x, v11 = acc[mt][nt][3] + bia.y;
            if (RES) {
                const float2 q0 = *(const float2*)(res + (size_t)r0 * N + col);
                const float2 q1 = *(const float2*)(res + (size_t)(r0 + 8) * N + col);
                v00 += q0.x; v01 += q0.y; v10 += q1.x; v11 += q1.y;
            }
            if (GELU) {
                v00 = 0.5f * v00 * (1.0f + erff(v00 * 0.70710678118654752f));
                v01 = 0.5f * v01 * (1.0f + erff(v01 * 0.70710678118654752f));
                v10 = 0.5f * v10 * (1.0f + erff(v10 * 0.70710678118654752f));
                v11 = 0.5f * v11 * (1.0f + erff(v11 * 0.70710678118654752f));
            }
            if (SCQ) { v00 *= qm; v01 *= qm; v10 *= qm; v11 *= qm; }
            if (OUTH) {
                __half* Ch = (__half*)Cv;
                *(__half2*)(Ch + (size_t)r0 * N + col)       = __floats2half2_rn(v00, v01);
                *(__half2*)(Ch + (size_t)(r0 + 8) * N + col) = __floats2half2_rn(v10, v11);
            } else {
                float* Cf = (float*)Cv;
                *(float2*)(Cf + (size_t)r0 * N + col)       = make_float2(v00, v01);
                *(float2*)(Cf + (size_t)(r0 + 8) * N + col) = make_float2(v10, v11);
            }
        }
    }
}

// ---------------- banded flash attention (fp16 mma, log2-domain softmax) ----------------
// Q pre-scaled by 0.125*log2(e) in QKV epilogue -> S is in log2 domain; ex2.approx only.
#define SATT_Q 0
#define SATT_K 16384
#define SATT_V 32768
#define SMEM_ATTN 49152

__global__ void __launch_bounds__(256, 2) attn_kernel(const __half* __restrict__ qkv,
                                                      __half* __restrict__ out)
{
    extern __shared__ char shm[];
    const uint32_t sbase = smem_u32(shm);
    const uint32_t sQ = sbase + SATT_Q;
    const uint32_t sK = sbase + SATT_K;
    const uint32_t sV = sbase + SATT_V;

    const int t    = threadIdx.x;
    const int lane = t & 31;
    const int w    = t >> 5;
    const int qs   = blockIdx.x * 128;
    const int h    = blockIdx.y;
    const int b    = blockIdx.z;
    const int bT   = b * Tn;
    const int h64  = h * HDm;

    const int l15 = lane & 15;
    const int lk  = lane >> 4;
    const int l7  = lane & 7;
    const int g   = lane >> 2;
    const int l4  = lane & 3;
    const int trow = ((lane >> 3) & 1) * 8 + (lane & 7);

    const int kt0 = (qs - WIN > 0) ? qs - WIN : 0;
    const int kt1 = (qs + 128 + WIN < Tn) ? qs + 128 + WIN : Tn;
    const int n   = (kt1 - kt0) >> 6;

    auto ldQ = [&]() {
#pragma unroll
        for (int i = 0; i < 4; i++) {
            const int idx = t + i * 256;
            const int r = idx >> 3, c = idx & 7;
            CPA16(sQ + r * 128 + ((c ^ (r & 7)) << 4),
                  qkv + (size_t)(bT + qs + r) * 2304 + h64 + c * 8);
        }
    };
    auto ldKV = [&](int tile, int s) {
#pragma unroll
        for (int i = 0; i < 2; i++) {
            const int idx = t + i * 256;
            const int key = idx >> 3, c = idx & 7;
            const uint32_t off = s * 8192 + key * 128 + ((c ^ (key & 7)) << 4);
            const __half* src = qkv + (size_t)(bT + kt0 + tile * 64 + key) * 2304 + h64 + c * 8;
            CPA16(sK + off, src + Dm);
            CPA16(sV + off, src + 2 * Dm);
        }
    };

    ldQ(); ldKV(0, 0); CPA_COMMIT();
    if (n > 1) ldKV(1, 1);
    CPA_COMMIT();

    float o[8][4];
#pragma unroll
    for (int j = 0; j < 8; j++)
#pragma unroll
        for (int q = 0; q < 4; q++) o[j][q] = 0.f;
    float m0 = -1e30f, m1 = -1e30f, l0 = 0.f, l1 = 0.f;

    const int qmin = qs + w * 16;
    const int q0 = qmin + g, q1 = q0 + 8;
    const uint32_t qb = sQ + (w * 16 + l15) * 128;

    for (int it = 0; it < n; it++) {
        const int s  = it & 1;
        const int kt = kt0 + it * 64;

        if (it + 1 < n) CPA_WAIT1(); else CPA_WAIT0();
        __syncthreads();

        // ---- S = Q @ K^T  (already in log2 domain via Q prescale) ----
        float sc[8][4];
#pragma unroll
        for (int j = 0; j < 8; j++)
#pragma unroll
            for (int q = 0; q < 4; q++) sc[j][q] = 0.f;

        const uint32_t kb_ = sK + s * 8192;
#pragma unroll
        for (int ks = 0; ks < 4; ks++) {
            const uint32_t sw = (uint32_t)(((2 * ks + lk) ^ l7) << 4);
            uint32_t qa[4];
            LDSM4(qa, qb + sw);
#pragma unroll
            for (int j2 = 0; j2 < 4; j2++) {
                uint32_t kb4[4];
                LDSM4(kb4, kb_ + (j2 * 16 + l15) * 128 + sw);
                MMA_F16(sc[2 * j2],     qa[0], qa[1], qa[2], qa[3], kb4[0], kb4[2]);
                MMA_F16(sc[2 * j2 + 1], qa[0], qa[1], qa[2], qa[3], kb4[1], kb4[3]);
            }
        }

        // ---- band mask + online softmax (log2 domain) ----
        const bool full = (kt >= qmin + 15 - WIN) && (kt + 63 <= qmin + WIN);
        float tm0 = -2e30f, tm1 = -2e30f;
#pragma unroll
        for (int j = 0; j < 8; j++) {
            if (!full) {
                const int kc = kt + 8 * j + 2 * l4;
                if (q0 - kc > WIN || kc - q0 > WIN)         sc[j][0] = -1e30f;
                if (q0 - kc - 1 > WIN || kc + 1 - q0 > WIN) sc[j][1] = -1e30f;
                if (q1 - kc > WIN || kc - q1 > WIN)         sc[j][2] = -1e30f;
                if (q1 - kc - 1 > WIN || kc + 1 - q1 > WIN) sc[j][3] = -1e30f;
            }
            tm0 = fmaxf(tm0, fmaxf(sc[j][0], sc[j][1]));
            tm1 = fmaxf(tm1, fmaxf(sc[j][2], sc[j][3]));
        }
        tm0 = fmaxf(tm0, __shfl_xor_sync(0xffffffffu, tm0, 1));
        tm0 = fmaxf(tm0, __shfl_xor_sync(0xffffffffu, tm0, 2));
        tm1 = fmaxf(tm1, __shfl_xor_sync(0xffffffffu, tm1, 1));
        tm1 = fmaxf(tm1, __shfl_xor_sync(0xffffffffu, tm1, 2));

        const float m0n = fmaxf(m0, tm0), m1n = fmaxf(m1, tm1);
        const float f0 = ex2f(m0 - m0n), f1 = ex2f(m1 - m1n);
        float s0 = 0.f, s1 = 0.f;
#pragma unroll
        for (int j = 0; j < 8; j++) {
            sc[j][0] = ex2f(sc[j][0] - m0n);
            sc[j][1] = ex2f(sc[j][1] - m0n);
            sc[j][2] = ex2f(sc[j][2] - m1n);
            sc[j][3] = ex2f(sc[j][3] - m1n);
            s0 += sc[j][0] + sc[j][1];
            s1 += sc[j][2] + sc[j][3];
        }
        s0 += __shfl_xor_sync(0xffffffffu, s0, 1);
        s0 += __shfl_xor_sync(0xffffffffu, s0, 2);
        s1 += __shfl_xor_sync(0xffffffffu, s1, 1);
        s1 += __shfl_xor_sync(0xffffffffu, s1, 2);
        l0 = l0 * f0 + s0;
        l1 = l1 * f1 + s1;
        m0 = m0n; m1 = m1n;
#pragma unroll
        for (int j = 0; j < 8; j++) {
            o[j][0] *= f0; o[j][1] *= f0; o[j][2] *= f1; o[j][3] *= f1;
        }

        // ---- O += P @ V ----
        const uint32_t vb_ = sV + s * 8192;
#pragma unroll
        for (int j2 = 0; j2 < 4; j2++) {
            const uint32_t a0 = packh2(sc[2 * j2][0],     sc[2 * j2][1]);
            const uint32_t a1 = packh2(sc[2 * j2][2],     sc[2 * j2][3]);
            const uint32_t a2 = packh2(sc[2 * j2 + 1][0], sc[2 * j2 + 1][1]);
            const uint32_t a3 = packh2(sc[2 * j2 + 1][2], sc[2 * j2 + 1][3]);
            const uint32_t vrow = vb_ + (j2 * 16 + trow) * 128;
#pragma unroll
            for (int v4 = 0; v4 < 4; v4++) {
                const uint32_t sw = (uint32_t)(((2 * v4 + lk) ^ l7) << 4);
                uint32_t vb4[4];
                LDSM4T(vb4, vrow + sw);
                MMA_F16(o[2 * v4],     a0, a1, a2, a3, vb4[0], vb4[1]);
                MMA_F16(o[2 * v4 + 1], a0, a1, a2, a3, vb4[2], vb4[3]);
            }
        }

        if (it + 2 < n) {
            __syncthreads();
            ldKV(it + 2, s);
        }
        CPA_COMMIT();
    }

    // ---- write fp16 output ----
    const float i0 = 1.0f / l0, i1 = 1.0f / l1;
    __half* o0 = out + (size_t)(bT + qs + w * 16 + g) * Dm + h64;
    __half* o1 = o0 + (size_t)8 * Dm;
#pragma unroll
    for (int j = 0; j < 8; j++) {
        const int col = 8 * j + 2 * l4;
        *(__half2*)(o0 + col) = __floats2half2_rn(o[j][0] * i0, o[j][1] * i0);
        *(__half2*)(o1 + col) = __floats2half2_rn(o[j][2] * i1, o[j][3] * i1);
    }
}

// ---------------- launch ----------------
extern "C" void kernel_launch(void* const* d_in, const int* in_sizes, int n_in,
                              void* d_out, int out_size)
{
    const float* x    = (const float*)d_in[0];
    const float* in_w = (const float*)d_in[1];
    const float* in_b = (const float*)d_in[2];
    const float* ow   = (const float*)d_in[3];
    const float* ob   = (const float*)d_in[4];
    const float* w1   = (const float*)d_in[5];
    const float* b1   = (const float*)d_in[6];
    const float* w2   = (const float*)d_in[7];
    const float* b2   = (const float*)d_in[8];
    const float* ln1g = (const float*)d_in[9];
    const float* ln1b = (const float*)d_in[10];
    const float* ln2g = (const float*)d_in[11];
    const float* ln2b = (const float*)d_in[12];
    float* out = (float*)d_out;

    __half *xnh, *qkvh, *attnh, *hh, *wqkvh, *owh, *w1h, *w2h;
    float* x1;
    cudaGetSymbolAddress((void**)&xnh,   g_xnh);
    cudaGetSymbolAddress((void**)&qkvh,  g_qkvh);
    cudaGetSymbolAddress((void**)&attnh, g_attnh);
    cudaGetSymbolAddress((void**)&hh,    g_hh);
    cudaGetSymbolAddress((void**)&x1,    g_x1);
    cudaGetSymbolAddress((void**)&wqkvh, g_wqkvh);
    cudaGetSymbolAddress((void**)&owh,   g_owh);
    cudaGetSymbolAddress((void**)&w1h,   g_w1h);
    cudaGetSymbolAddress((void**)&w2h,   g_w2h);

    const int SMEM128 = STAGES * (128 * 128 + BSTG);  // 98304
    const int SMEM64  = STAGES * (64 * 128 + BSTG);   // 73728

    cudaFuncSetAttribute(attn_kernel, cudaFuncAttributeMaxDynamicSharedMemorySize, SMEM_ATTN);
    cudaFuncSetAttribute(gemm_h_kernel<0, 0, 1, 128, 1>, cudaFuncAttributeMaxDynamicSharedMemorySize, SMEM128);
    cudaFuncSetAttribute(gemm_h_kernel<1, 0, 1, 128, 0>, cudaFuncAttributeMaxDynamicSharedMemorySize, SMEM128);
    cudaFuncSetAttribute(gemm_h_kernel<0, 1, 0, 64, 0>,  cudaFuncAttributeMaxDynamicSharedMemorySize, SMEM64);

    // 0) fused weight conversion fp32 -> fp16
    f2h4_kernel<<<3456, 256>>>(in_w, ow, w1, w2, wqkvh, owh, w1h, w2h);

    // 1) LN1 -> fp16 (2 rows per CTA)
    ln_kernel<<<NT / 2, 384>>>(x, ln1g, ln1b, xnh);
    // 2) QKV projection -> fp16, Q columns pre-scaled for log2-domain softmax
    gemm_h_kernel<0, 0, 1, 128, 1><<<dim3(3 * Dm / BN, NT / 128), 256, SMEM128>>>(
        xnh, wqkvh, in_b, nullptr, qkvh, NT, 3 * Dm, Dm);
    // 3) banded attention -> fp16
    attn_kernel<<<dim3(Tn / 128, Hn, Bsz), 256, SMEM_ATTN>>>(qkvh, attnh);
    // 4) out projection + residual -> fp32 x1
    gemm_h_kernel<0, 1, 0, 64, 0><<<dim3(Dm / BN, NT / 64), 256, SMEM64>>>(
        attnh, owh, ob, x, x1, NT, Dm, Dm);
    // 5) LN2 -> fp16
    ln_kernel<<<NT / 2, 384>>>(x1, ln2g, ln2b, xnh);
    // 6) MLP up + GELU -> fp16
    gemm_h_kernel<1, 0, 1, 128, 0><<<dim3(MLPD / BN, NT / 128), 256, SMEM128>>>(
        xnh, w1h, b1, nullptr, hh, NT, MLPD, Dm);
    // 7) MLP down + residual -> fp32 d_out
    gemm_h_kernel<0, 1, 0, 64, 0><<<dim3(Dm / BN, NT / 64), 256, SMEM64>>>(
        hh, w2h, b2, x1, out, NT, Dm, MLPD);
}

// round 14
// speedup vs baseline: 1.5410x; 1.5410x over previous
#include <cuda_runtime.h>
#include <cuda_fp16.h>
#include <math.h>
#include <stdint.h>

#define Bsz  4
#define Tn   2048
#define Dm   768
#define Hn   12
#define HDm  64
#define MLPD 3072
#define WIN  256
#define NT   (Bsz * Tn)   /* 8192 rows */

#define QSC 0.18033688011112043f   /* 0.125 * log2(e) */

// ---------------- static scratch ----------------
__device__ __half g_xnh  [NT * Dm];
__device__ __half g_qkvh [NT * 3 * Dm];
__device__ __half g_attnh[NT * Dm];
__device__ __half g_hh   [NT * MLPD];
__device__ float  g_x1   [NT * Dm];
__device__ __half g_wqkvh[3 * Dm * Dm];
__device__ __half g_owh  [Dm * Dm];
__device__ __half g_w1h  [MLPD * Dm];
__device__ __half g_w2h  [Dm * MLPD];

__device__ __forceinline__ uint32_t smem_u32(const void* p) {
    uint32_t a;
    asm("{ .reg .u64 t; cvta.to.shared.u64 t, %1; cvt.u32.u64 %0, t; }"
        : "=r"(a) : "l"(p));
    return a;
}
__device__ __forceinline__ float ex2f(float x) {
    float y;
    asm("ex2.approx.f32 %0, %1;" : "=f"(y) : "f"(x));
    return y;
}

#define CPA16(dst, src) \
    asm volatile("cp.async.cg.shared.global [%0], [%1], 16;" \
                 :: "r"(dst), "l"(src) : "memory")
#define CPA_COMMIT() asm volatile("cp.async.commit_group;" ::: "memory")
#define CPA_WAIT1()  asm volatile("cp.async.wait_group 1;" ::: "memory")
#define CPA_WAIT0()  asm volatile("cp.async.wait_group 0;" ::: "memory")

#define LDSM4(r, addr)                                                        \
    asm volatile("ldmatrix.sync.aligned.m8n8.x4.shared.b16 {%0,%1,%2,%3}, [%4];" \
        : "=r"((r)[0]), "=r"((r)[1]), "=r"((r)[2]), "=r"((r)[3]) : "r"(addr))
#define LDSM4T(r, addr)                                                       \
    asm volatile("ldmatrix.sync.aligned.m8n8.x4.trans.shared.b16 {%0,%1,%2,%3}, [%4];" \
        : "=r"((r)[0]), "=r"((r)[1]), "=r"((r)[2]), "=r"((r)[3]) : "r"(addr))

#define MMA_F16(c, A0, A1, A2, A3, B0, B1)                               \
    asm volatile(                                                        \
        "mma.sync.aligned.m16n8k16.row.col.f32.f16.f16.f32 "             \
        "{%0,%1,%2,%3}, {%4,%5,%6,%7}, {%8,%9}, {%0,%1,%2,%3};"          \
        : "+f"((c)[0]), "+f"((c)[1]), "+f"((c)[2]), "+f"((c)[3])         \
        : "r"(A0), "r"(A1), "r"(A2), "r"(A3), "r"(B0), "r"(B1))

__device__ __forceinline__ uint32_t packh2(float a, float b) {
    __half2 h = __floats2half2_rn(a, b);
    return *(uint32_t*)&h;
}

// ---------------- fused fp32 -> fp16 conversion (all 4 weight tensors) ----------------
__global__ void __launch_bounds__(256) f2h4_kernel(
    const float* __restrict__ s0, const float* __restrict__ s1,
    const float* __restrict__ s2, const float* __restrict__ s3,
    __half* __restrict__ d0, __half* __restrict__ d1,
    __half* __restrict__ d2, __half* __restrict__ d3)
{
    int blk = blockIdx.x;
    const float* s; __half* d;
    if      (blk < 864)  { s = s0; d = d0; }
    else if (blk < 1152) { s = s1; d = d1; blk -= 864; }
    else if (blk < 2304) { s = s2; d = d2; blk -= 1152; }
    else                 { s = s3; d = d3; blk -= 2304; }
    const int i = blk * 2048 + threadIdx.x * 8;
    const float4 a = *(const float4*)(s + i);
    const float4 b = *(const float4*)(s + i + 4);
    *(__half2*)(d + i)     = __floats2half2_rn(a.x, a.y);
    *(__half2*)(d + i + 2) = __floats2half2_rn(a.z, a.w);
    *(__half2*)(d + i + 4) = __floats2half2_rn(b.x, b.y);
    *(__half2*)(d + i + 6) = __floats2half2_rn(b.z, b.w);
}

// ---------------- LayerNorm (fp32 in -> fp16 out), float4 vectorized ----------------
__global__ void __launch_bounds__(192) ln_kernel(const float* __restrict__ x,
                                                 const float* __restrict__ g,
                                                 const float* __restrict__ b,
                                                 __half* __restrict__ y)
{
    const int row = blockIdx.x;
    const int t = threadIdx.x;
    const float4 v = *(const float4*)(x + (size_t)row * Dm + t * 4);

    float s  = v.x + v.y + v.z + v.w;
    float s2 = v.x * v.x + v.y * v.y + v.z * v.z + v.w * v.w;
    __shared__ float red[12];
#pragma unroll
    for (int o = 16; o > 0; o >>= 1) {
        s  += __shfl_xor_sync(0xffffffffu, s,  o);
        s2 += __shfl_xor_sync(0xffffffffu, s2, o);
    }
    const int w = t >> 5;
    if ((t & 31) == 0) { red[w] = s; red[6 + w] = s2; }
    __syncthreads();
    s = 0.f; s2 = 0.f;
#pragma unroll
    for (int i = 0; i < 6; i++) { s += red[i]; s2 += red[6 + i]; }

    const float mean = s * (1.0f / Dm);
    float var = s2 * (1.0f / Dm) - mean * mean;
    var = fmaxf(var, 0.0f);
    const float rstd = rsqrtf(var + 1e-5f);

    const float4 g4 = *(const float4*)(g + t * 4);
    const float4 b4 = *(const float4*)(b + t * 4);
    __half* yr = y + (size_t)row * Dm + t * 4;
    *(__half2*)(yr)     = __floats2half2_rn((v.x - mean) * rstd * g4.x + b4.x,
                                            (v.y - mean) * rstd * g4.y + b4.y);
    *(__half2*)(yr + 2) = __floats2half2_rn((v.z - mean) * rstd * g4.z + b4.z,
                                            (v.w - mean) * rstd * g4.w + b4.w);
}

// ---------------- fp16 GEMM: cp.async + ldmatrix + mma.m16n8k16 ----------------
// C[M,N] = A[M,K] @ B[N,K]^T + bias (+res) (+gelu) (+Q prescale). TBM = 128 or 64.
#define BN 128
#define BKH 64
#define STAGES 3
#define BSTG 16384

template<int GELU, int RES, int OUTH, int TBM, int SCQ>
__global__ void __launch_bounds__(256, 2) gemm_h_kernel(
    const __half* __restrict__ A,
    const __half* __restrict__ B,
    const float* __restrict__ bias,
    const float* __restrict__ res,
    void* __restrict__ Cv,
    int M, int N, int K)
{
    constexpr int WROWS = TBM / 2;
    constexpr int MT    = WROWS / 16;
    constexpr int AIT   = TBM / 32;
    constexpr int ASTG  = TBM * 128;

    extern __shared__ char sh[];
    const uint32_t sA = smem_u32(sh);
    const uint32_t sB = sA + STAGES * ASTG;

    const int t    = threadIdx.x;
    const int lane = t & 31;
    const int warp = t >> 5;
    const int wm   = warp & 1;
    const int wn   = warp >> 1;
    const int bm   = blockIdx.y * TBM;
    const int bn   = blockIdx.x * BN;

    const int cm  = t >> 3;
    const int ckq = t & 7;
    const uint32_t daBase = cm * 128 + (uint32_t)((ckq ^ (cm & 7)) << 4);
    const __half* Ag = A + (size_t)(bm + cm) * K + ckq * 8;
    const __half* Bg = B + (size_t)(bn + cm) * K + ckq * 8;

    const int l15 = lane & 15;
    const int lk  = lane >> 4;
    const int l7  = lane & 7;
    uint32_t aoff[MT], boff[2];
#pragma unroll
    for (int mt = 0; mt < MT; mt++) aoff[mt] = (uint32_t)((wm * WROWS + mt * 16 + l15) * 128);
#pragma unroll
    for (int n2 = 0; n2 < 2; n2++) boff[n2] = (uint32_t)((wn * 32 + n2 * 16 + l15) * 128);

    float acc[MT][4][4];
#pragma unroll
    for (int mt = 0; mt < MT; mt++)
#pragma unroll
        for (int nt = 0; nt < 4; nt++)
#pragma unroll
            for (int q = 0; q < 4; q++) acc[mt][nt][q] = 0.f;

    const int nch = K / BKH;

    auto issue = [&](int ch, int s) {
        const __half* ag = Ag + ch * BKH;
        const __half* bg = Bg + ch * BKH;
        const uint32_t da = sA + s * ASTG + daBase;
        const uint32_t db = sB + s * BSTG + daBase;
#pragma unroll
        for (int i = 0; i < AIT; i++)
            CPA16(da + i * 32 * 128, ag + (size_t)i * 32 * K);
#pragma unroll
        for (int i = 0; i < 4; i++)
            CPA16(db + i * 32 * 128, bg + (size_t)i * 32 * K);
    };

    issue(0, 0); CPA_COMMIT();
    issue(1, 1); CPA_COMMIT();

    for (int ch = 0; ch < nch; ch++) {
        CPA_WAIT1();
        __syncthreads();
        if (ch + 2 < nch) issue(ch + 2, (ch + 2) % STAGES);
        CPA_COMMIT();

        const uint32_t baA = sA + (ch % STAGES) * ASTG;
        const uint32_t baB = sB + (ch % STAGES) * BSTG;
#pragma unroll
        for (int ks = 0; ks < 4; ks++) {
            const uint32_t sw = (uint32_t)(((2 * ks + lk) ^ l7) << 4);
            uint32_t a[MT][4], b[2][4];
#pragma unroll
            for (int mt = 0; mt < MT; mt++) LDSM4(a[mt], baA + aoff[mt] + sw);
#pragma unroll
            for (int n2 = 0; n2 < 2; n2++) LDSM4(b[n2], baB + boff[n2] + sw);
#pragma unroll
            for (int mt = 0; mt < MT; mt++)
#pragma unroll
                for (int nt = 0; nt < 4; nt++)
                    MMA_F16(acc[mt][nt],
                            a[mt][0], a[mt][1], a[mt][2], a[mt][3],
                            b[nt >> 1][nt & 1], b[nt >> 1][2 + (nt & 1)]);
        }
    }

    // ---- epilogue ----
    const int g  = lane >> 2;
    const int l4 = lane & 3;
    const float qm = (SCQ && bn < Dm) ? QSC : 1.0f;   // prescale Q columns (log2-domain softmax)
#pragma unroll
    for (int mt = 0; mt < MT; mt++) {
        const int r0 = bm + wm * WROWS + mt * 16 + g;
#pragma unroll
        for (int nt = 0; nt < 4; nt++) {
            const int col = bn + wn * 32 + nt * 8 + l4 * 2;
            const float2 bia = *(const float2*)(bias + col);
            float v00 = acc[mt][nt][0] + bia.x, v01 = acc[mt][nt][1] + bia.y;
            float v10 = acc[mt][nt][2] + bia.x, v11 = acc[mt][nt][3] + bia.y;
            if (RES) {
                const float2 q0 = *(const float2*)(res + (size_t)r0 * N + col);
                const float2 q1 = *(const float2*)(res + (size_t)(r0 + 8) * N + col);
                v00 += q0.x; v01 += q0.y; v10 += q1.x; v11 += q1.y;
            }
            if (GELU) {
                v00 = 0.5f * v00 * (1.0f + erff(v00 * 0.70710678118654752f));
                v01 = 0.5f * v01 * (1.0f + erff(v01 * 0.70710678118654752f));
                v10 = 0.5f * v10 * (1.0f + erff(v10 * 0.70710678118654752f));
                v11 = 0.5f * v11 * (1.0f + erff(v11 * 0.70710678118654752f));
            }
            if (SCQ) { v00 *= qm; v01 *= qm; v10 *= qm; v11 *= qm; }
            if (OUTH) {
                __half* Ch = (__half*)Cv;
                *(__half2*)(Ch + (size_t)r0 * N + col)       = __floats2half2_rn(v00, v01);
                *(__half2*)(Ch + (size_t)(r0 + 8) * N + col) = __floats2half2_rn(v10, v11);
            } else {
                float* Cf = (float*)Cv;
                *(float2*)(Cf + (size_t)r0 * N + col)       = make_float2(v00, v01);
                *(float2*)(Cf + (size_t)(r0 + 8) * N + col) = make_float2(v10, v11);
            }
        }
    }
}

// ---------------- banded flash attention (fp16 mma, log2-domain softmax) ----------------
#define SATT_Q 0
#define SATT_K 16384
#define SATT_V 32768
#define SMEM_ATTN 49152

__global__ void __launch_bounds__(256, 2) attn_kernel(const __half* __restrict__ qkv,
                                                      __half* __restrict__ out)
{
    extern __shared__ char shm[];
    const uint32_t sbase = smem_u32(shm);
    const uint32_t sQ = sbase + SATT_Q;
    const uint32_t sK = sbase + SATT_K;
    const uint32_t sV = sbase + SATT_V;

    const int t    = threadIdx.x;
    const int lane = t & 31;
    const int w    = t >> 5;
    const int qs   = blockIdx.x * 128;
    const int h    = blockIdx.y;
    const int b    = blockIdx.z;
    const int bT   = b * Tn;
    const int h64  = h * HDm;

    const int l15 = lane & 15;
    const int lk  = lane >> 4;
    const int l7  = lane & 7;
    const int g   = lane >> 2;
    const int l4  = lane & 3;
    const int trow = ((lane >> 3) & 1) * 8 + (lane & 7);

    const int kt0 = (qs - WIN > 0) ? qs - WIN : 0;
    const int kt1 = (qs + 128 + WIN < Tn) ? qs + 128 + WIN : Tn;
    const int n   = (kt1 - kt0) >> 6;

    auto ldQ = [&]() {
#pragma unroll
        for (int i = 0; i < 4; i++) {
            const int idx = t + i * 256;
            const int r = idx >> 3, c = idx & 7;
            CPA16(sQ + r * 128 + ((c ^ (r & 7)) << 4),
                  qkv + (size_t)(bT + qs + r) * 2304 + h64 + c * 8);
        }
    };
    auto ldKV = [&](int tile, int s) {
#pragma unroll
        for (int i = 0; i < 2; i++) {
            const int idx = t + i * 256;
            const int key = idx >> 3, c = idx & 7;
            const uint32_t off = s * 8192 + key * 128 + ((c ^ (key & 7)) << 4);
            const __half* src = qkv + (size_t)(bT + kt0 + tile * 64 + key) * 2304 + h64 + c * 8;
            CPA16(sK + off, src + Dm);
            CPA16(sV + off, src + 2 * Dm);
        }
    };

    ldQ(); ldKV(0, 0); CPA_COMMIT();
    if (n > 1) ldKV(1, 1);
    CPA_COMMIT();

    float o[8][4];
#pragma unroll
    for (int j = 0; j < 8; j++)
#pragma unroll
        for (int q = 0; q < 4; q++) o[j][q] = 0.f;
    float m0 = -1e30f, m1 = -1e30f, l0 = 0.f, l1 = 0.f;

    const int qmin = qs + w * 16;
    const int q0 = qmin + g, q1 = q0 + 8;
    const uint32_t qb = sQ + (w * 16 + l15) * 128;

    for (int it = 0; it < n; it++) {
        const int s  = it & 1;
        const int kt = kt0 + it * 64;

        if (it + 1 < n) CPA_WAIT1(); else CPA_WAIT0();
        __syncthreads();

        // ---- S = Q @ K^T  (already in log2 domain via Q prescale) ----
        float sc[8][4];
#pragma unroll
        for (int j = 0; j < 8; j++)
#pragma unroll
            for (int q = 0; q < 4; q++) sc[j][q] = 0.f;

        const uint32_t kb_ = sK + s * 8192;
#pragma unroll
        for (int ks = 0; ks < 4; ks++) {
            const uint32_t sw = (uint32_t)(((2 * ks + lk) ^ l7) << 4);
            uint32_t qa[4];
            LDSM4(qa, qb + sw);
#pragma unroll
            for (int j2 = 0; j2 < 4; j2++) {
                uint32_t kb4[4];
                LDSM4(kb4, kb_ + (j2 * 16 + l15) * 128 + sw);
                MMA_F16(sc[2 * j2],     qa[0], qa[1], qa[2], qa[3], kb4[0], kb4[2]);
                MMA_F16(sc[2 * j2 + 1], qa[0], qa[1], qa[2], qa[3], kb4[1], kb4[3]);
            }
        }

        // ---- band mask + online softmax (log2 domain) ----
        const bool full = (kt >= qmin + 15 - WIN) && (kt + 63 <= qmin + WIN);
        float tm0 = -2e30f, tm1 = -2e30f;
#pragma unroll
        for (int j = 0; j < 8; j++) {
            if (!full) {
                const int kc = kt + 8 * j + 2 * l4;
                if (q0 - kc > WIN || kc - q0 > WIN)         sc[j][0] = -2e30f;
                if (q0 - kc - 1 > WIN || kc + 1 - q0 > WIN) sc[j][1] = -2e30f;
                if (q1 - kc > WIN || kc - q1 > WIN)         sc[j][2] = -2e30f;
                if (q1 - kc - 1 > WIN || kc + 1 - q1 > WIN) sc[j][3] = -2e30f;
            }
            tm0 = fmaxf(tm0, fmaxf(sc[j][0], sc[j][1]));
            tm1 = fmaxf(tm1, fmaxf(sc[j][2], sc[j][3]));
        }
        tm0 = fmaxf(tm0, __shfl_xor_sync(0xffffffffu, tm0, 1));
        tm0 = fmaxf(tm0, __shfl_xor_sync(0xffffffffu, tm0, 2));
        tm1 = fmaxf(tm1, __shfl_xor_sync(0xffffffffu, tm1, 1));
        tm1 = fmaxf(tm1, __shfl_xor_sync(0xffffffffu, tm1, 2));

        const float m0n = fmaxf(m0, tm0), m1n = fmaxf(m1, tm1);
        const float f0 = ex2f(m0 - m0n), f1 = ex2f(m1 - m1n);
        float s0 = 0.f, s1 = 0.f;
#pragma unroll
        for (int j = 0; j < 8; j++) {
            sc[j][0] = ex2f(sc[j][0] - m0n);
            sc[j][1] = ex2f(sc[j][1] - m0n);
            sc[j][2] = ex2f(sc[j][2] - m1n);
            sc[j][3] = ex2f(sc[j][3] - m1n);
            s0 += sc[j][0] + sc[j][1];
            s1 += sc[j][2] + sc[j][3];
        }
        s0 += __shfl_xor_sync(0xffffffffu, s0, 1);
        s0 += __shfl_xor_sync(0xffffffffu, s0, 2);
        s1 += __shfl_xor_sync(0xffffffffu, s1, 1);
        s1 += __shfl_xor_sync(0xffffffffu, s1, 2);
        l0 = l0 * f0 + s0;
        l1 = l1 * f1 + s1;
        m0 = m0n; m1 = m1n;
#pragma unroll
        for (int j = 0; j < 8; j++) {
            o[j][0] *= f0; o[j][1] *= f0; o[j][2] *= f1; o[j][3] *= f1;
        }

        // ---- O += P @ V ----
        const uint32_t vb_ = sV + s * 8192;
#pragma unroll
        for (int j2 = 0; j2 < 4; j2++) {
            const uint32_t a0 = packh2(sc[2 * j2][0],     sc[2 * j2][1]);
            const uint32_t a1 = packh2(sc[2 * j2][2],     sc[2 * j2][3]);
            const uint32_t a2 = packh2(sc[2 * j2 + 1][0], sc[2 * j2 + 1][1]);
            const uint32_t a3 = packh2(sc[2 * j2 + 1][2], sc[2 * j2 + 1][3]);
            const uint32_t vrow = vb_ + (j2 * 16 + trow) * 128;
#pragma unroll
            for (int v4 = 0; v4 < 4; v4++) {
                const uint32_t sw = (uint32_t)(((2 * v4 + lk) ^ l7) << 4);
                uint32_t vb4[4];
                LDSM4T(vb4, vrow + sw);
                MMA_F16(o[2 * v4],     a0, a1, a2, a3, vb4[0], vb4[1]);
                MMA_F16(o[2 * v4 + 1], a0, a1, a2, a3, vb4[2], vb4[3]);
            }
        }

        if (it + 2 < n) {
            __syncthreads();
            ldKV(it + 2, s);
        }
        CPA_COMMIT();
    }

    // ---- write fp16 output ----
    const float i0 = 1.0f / l0, i1 = 1.0f / l1;
    __half* o0 = out + (size_t)(bT + qs + w * 16 + g) * Dm + h64;
    __half* o1 = o0 + (size_t)8 * Dm;
#pragma unroll
    for (int j = 0; j < 8; j++) {
        const int col = 8 * j + 2 * l4;
        *(__half2*)(o0 + col) = __floats2half2_rn(o[j][0] * i0, o[j][1] * i0);
        *(__half2*)(o1 + col) = __floats2half2_rn(o[j][2] * i1, o[j][3] * i1);
    }
}

// ---------------- launch ----------------
extern "C" void kernel_launch(void* const* d_in, const int* in_sizes, int n_in,
                              void* d_out, int out_size)
{
    const float* x    = (const float*)d_in[0];
    const float* in_w = (const float*)d_in[1];
    const float* in_b = (const float*)d_in[2];
    const float* ow   = (const float*)d_in[3];
    const float* ob   = (const float*)d_in[4];
    const float* w1   = (const float*)d_in[5];
    const float* b1   = (const float*)d_in[6];
    const float* w2   = (const float*)d_in[7];
    const float* b2   = (const float*)d_in[8];
    const float* ln1g = (const float*)d_in[9];
    const float* ln1b = (const float*)d_in[10];
    const float* ln2g = (const float*)d_in[11];
    const float* ln2b = (const float*)d_in[12];
    float* out = (float*)d_out;

    __half *xnh, *qkvh, *attnh, *hh, *wqkvh, *owh, *w1h, *w2h;
    float* x1;
    cudaGetSymbolAddress((void**)&xnh,   g_xnh);
    cudaGetSymbolAddress((void**)&qkvh,  g_qkvh);
    cudaGetSymbolAddress((void**)&attnh, g_attnh);
    cudaGetSymbolAddress((void**)&hh,    g_hh);
    cudaGetSymbolAddress((void**)&x1,    g_x1);
    cudaGetSymbolAddress((void**)&wqkvh, g_wqkvh);
    cudaGetSymbolAddress((void**)&owh,   g_owh);
    cudaGetSymbolAddress((void**)&w1h,   g_w1h);
    cudaGetSymbolAddress((void**)&w2h,   g_w2h);

    const int SMEM128 = STAGES * (128 * 128 + BSTG);  // 98304
    const int SMEM64  = STAGES * (64 * 128 + BSTG);   // 73728

    cudaFuncSetAttribute(attn_kernel, cudaFuncAttributeMaxDynamicSharedMemorySize, SMEM_ATTN);
    cudaFuncSetAttribute(gemm_h_kernel<0, 0, 1, 128, 1>, cudaFuncAttributeMaxDynamicSharedMemorySize, SMEM128);
    cudaFuncSetAttribute(gemm_h_kernel<1, 0, 1, 128, 0>, cudaFuncAttributeMaxDynamicSharedMemorySize, SMEM128);
    cudaFuncSetAttribute(gemm_h_kernel<0, 1, 0, 64, 0>,  cudaFuncAttributeMaxDynamicSharedMemorySize, SMEM64);

    // 0) fused weight conversion fp32 -> fp16
    f2h4_kernel<<<3456, 256>>>(in_w, ow, w1, w2, wqkvh, owh, w1h, w2h);

    // 1) LN1 -> fp16
    ln_kernel<<<NT, 192>>>(x, ln1g, ln1b, xnh);
    // 2) QKV projection -> fp16, Q columns pre-scaled for log2-domain softmax
    gemm_h_kernel<0, 0, 1, 128, 1><<<dim3(3 * Dm / BN, NT / 128), 256, SMEM128>>>(
        xnh, wqkvh, in_b, nullptr, qkvh, NT, 3 * Dm, Dm);
    // 3) banded attention -> fp16
    attn_kernel<<<dim3(Tn / 128, Hn, Bsz), 256, SMEM_ATTN>>>(qkvh, attnh);
    // 4) out projection + residual -> fp32 x1
    gemm_h_kernel<0, 1, 0, 64, 0><<<dim3(Dm / BN, NT / 64), 256, SMEM64>>>(
        attnh, owh, ob, x, x1, NT, Dm, Dm);
    // 5) LN2 -> fp16
    ln_kernel<<<NT, 192>>>(x1, ln2g, ln2b, xnh);
    // 6) MLP up + GELU -> fp16
    gemm_h_kernel<1, 0, 1, 128, 0><<<dim3(MLPD / BN, NT / 128), 256, SMEM128>>>(
        xnh, w1h, b1, nullptr, hh, NT, MLPD, Dm);
    // 7) MLP down + residual -> fp32 d_out
    gemm_h_kernel<0, 1, 0, 64, 0><<<dim3(Dm / BN, NT / 64), 256, SMEM64>>>(
        hh, w2h, b2, x1, out, NT, Dm, MLPD);
}